// round 1
// baseline (speedup 1.0000x reference)
#include <cuda_runtime.h>
#include <math.h>

#define NN 50000
#define HH 128
#define EE 600000
#define GG 256
#define OUTD 64
#define NITER 5
#define GAMMA 0.1f
#define EPS 0.1f
#define SLOPE 0.01f

// ---------------- device scratch (static, allocation-free) ----------------
__device__ float g_x[NN * HH];        // working node features
__device__ float g_nc[NN * 256];      // [neigh(0:128) | conv_lin(128:256)] per row
__device__ float g_Wcat[HH * 256];    // concatenated weight: [lin_w^T | A^T]
__device__ int   g_counts[NN];
__device__ int   g_rowptr[NN + 1];
__device__ int   g_fillptr[NN];
__device__ int   g_srcsorted[EE];
__device__ int   g_gstart[GG + 1];
__device__ float g_pooled[GG * 384];
__device__ float g_h[GG * 192];

// ---------------- prep kernels ----------------
__global__ void wcat_kernel(const float* __restrict__ W, const float* __restrict__ lin_w) {
    int k = blockIdx.x;      // 0..127
    int j = threadIdx.x;     // 0..255
    float v;
    if (j < 128) {
        // neigh col j: sum_k x[k]*lin_w[j,k]
        v = lin_w[j * HH + k];
    } else {
        int jp = j - 128;
        // conv col jp: A[jp,k] = W[jp,k] - W[k,jp] - gamma*(jp==k)
        v = W[jp * HH + k] - W[k * HH + jp] - (jp == k ? GAMMA : 0.0f);
    }
    g_Wcat[k * 256 + j] = v;
}

__global__ void copy_x_kernel(const float* __restrict__ xin) {
    int i = blockIdx.x * blockDim.x + threadIdx.x;
    if (i < NN * HH / 4) {
        reinterpret_cast<float4*>(g_x)[i] = reinterpret_cast<const float4*>(xin)[i];
    }
}

__global__ void zero_counts_kernel() {
    int i = blockIdx.x * blockDim.x + threadIdx.x;
    if (i < NN) g_counts[i] = 0;
}

__global__ void hist_kernel(const int* __restrict__ ei) {
    int e = blockIdx.x * blockDim.x + threadIdx.x;
    if (e < EE) {
        int dst = ei[EE + e];
        atomicAdd(&g_counts[dst], 1);
    }
}

__global__ void scan_kernel() {
    __shared__ int sh[1024];
    __shared__ int s_running;
    int t = threadIdx.x;
    if (t == 0) s_running = 0;
    __syncthreads();
    for (int base = 0; base < NN; base += 1024) {
        int i = base + t;
        int v = (i < NN) ? g_counts[i] : 0;
        sh[t] = v;
        __syncthreads();
        #pragma unroll
        for (int off = 1; off < 1024; off <<= 1) {
            int add = (t >= off) ? sh[t - off] : 0;
            __syncthreads();
            sh[t] += add;
            __syncthreads();
        }
        int incl = sh[t];
        int run = s_running;
        if (i < NN) {
            int excl = run + incl - v;
            g_rowptr[i] = excl;
            g_fillptr[i] = excl;
        }
        __syncthreads();
        if (t == 1023) s_running = run + incl;
        __syncthreads();
    }
    if (t == 0) g_rowptr[NN] = EE;
}

__global__ void fill_kernel(const int* __restrict__ ei) {
    int e = blockIdx.x * blockDim.x + threadIdx.x;
    if (e < EE) {
        int src = ei[e];
        int dst = ei[EE + e];
        int pos = atomicAdd(&g_fillptr[dst], 1);
        g_srcsorted[pos] = src;
    }
}

// ---------------- GEMM: g_nc = g_x [NN,128] @ g_Wcat [128,256] ----------------
// 64x64 tile, 256 threads, 4x4 microtile, packed f32x2 FMAs.
__global__ __launch_bounds__(256) void gemm_kernel() {
    __shared__ float Xs[64][64];   // transposed: [k][m]
    __shared__ float Ws[64][64];   // [k][n]
    int tid = threadIdx.x;
    int tx = tid & 15;
    int ty = tid >> 4;
    int rowbase = blockIdx.x * 64;
    int colbase = blockIdx.y * 64;

    unsigned long long acc[4][2];
    #pragma unroll
    for (int i = 0; i < 4; i++) { acc[i][0] = 0ull; acc[i][1] = 0ull; }

    for (int kk = 0; kk < 128; kk += 64) {
        // load X tile transposed into Xs[k][m]
        #pragma unroll
        for (int p = 0; p < 4; p++) {
            int idx = tid + p * 256;      // 0..1023 float4 slots
            int m = idx & 63;
            int kq = (idx >> 6) * 4;      // 0..60
            int grow = rowbase + m;
            float4 f = make_float4(0.f, 0.f, 0.f, 0.f);
            if (grow < NN) f = *reinterpret_cast<const float4*>(&g_x[grow * HH + kk + kq]);
            Xs[kq + 0][m] = f.x; Xs[kq + 1][m] = f.y;
            Xs[kq + 2][m] = f.z; Xs[kq + 3][m] = f.w;
        }
        // load W tile into Ws[k][n]
        #pragma unroll
        for (int p = 0; p < 4; p++) {
            int idx = tid + p * 256;
            int k = idx >> 4;             // 0..63
            int nq = (idx & 15) * 4;      // 0..60
            float4 f = *reinterpret_cast<const float4*>(&g_Wcat[(kk + k) * 256 + colbase + nq]);
            *reinterpret_cast<float4*>(&Ws[k][nq]) = f;
        }
        __syncthreads();
        #pragma unroll
        for (int k = 0; k < 64; k++) {
            float4 av = *reinterpret_cast<const float4*>(&Xs[k][ty * 4]);
            unsigned long long b01 = *reinterpret_cast<const unsigned long long*>(&Ws[k][tx * 4]);
            unsigned long long b23 = *reinterpret_cast<const unsigned long long*>(&Ws[k][tx * 4 + 2]);
            float a_arr[4] = {av.x, av.y, av.z, av.w};
            #pragma unroll
            for (int i = 0; i < 4; i++) {
                unsigned long long a2;
                asm("mov.b64 %0, {%1, %1};" : "=l"(a2) : "f"(a_arr[i]));
                asm("fma.rn.f32x2 %0, %1, %2, %0;" : "+l"(acc[i][0]) : "l"(a2), "l"(b01));
                asm("fma.rn.f32x2 %0, %1, %2, %0;" : "+l"(acc[i][1]) : "l"(a2), "l"(b23));
            }
        }
        __syncthreads();
    }
    #pragma unroll
    for (int i = 0; i < 4; i++) {
        int row = rowbase + ty * 4 + i;
        if (row < NN) {
            float c0, c1, c2, c3;
            asm("mov.b64 {%0, %1}, %2;" : "=f"(c0), "=f"(c1) : "l"(acc[i][0]));
            asm("mov.b64 {%0, %1}, %2;" : "=f"(c2), "=f"(c3) : "l"(acc[i][1]));
            float4 o = make_float4(c0, c1, c2, c3);
            *reinterpret_cast<float4*>(&g_nc[row * 256 + colbase + tx * 4]) = o;
        }
    }
}

// ---------------- fused aggregate + conv + tanh + x update (warp per node) ----------------
__global__ __launch_bounds__(256) void agg_update_kernel(const float* __restrict__ bias) {
    int node = (blockIdx.x * blockDim.x + threadIdx.x) >> 5;
    int lane = threadIdx.x & 31;
    if (node >= NN) return;
    int s = g_rowptr[node];
    int e = g_rowptr[node + 1];
    float4 acc0 = make_float4(0.f, 0.f, 0.f, 0.f);
    float4 acc1 = make_float4(0.f, 0.f, 0.f, 0.f);
    int p = s;
    for (; p + 1 < e; p += 2) {
        int s0 = g_srcsorted[p];
        int s1 = g_srcsorted[p + 1];
        float4 v0 = *reinterpret_cast<const float4*>(&g_nc[s0 * 256 + lane * 4]);
        float4 v1 = *reinterpret_cast<const float4*>(&g_nc[s1 * 256 + lane * 4]);
        acc0.x += v0.x; acc0.y += v0.y; acc0.z += v0.z; acc0.w += v0.w;
        acc1.x += v1.x; acc1.y += v1.y; acc1.z += v1.z; acc1.w += v1.w;
    }
    if (p < e) {
        int s0 = g_srcsorted[p];
        float4 v0 = *reinterpret_cast<const float4*>(&g_nc[s0 * 256 + lane * 4]);
        acc0.x += v0.x; acc0.y += v0.y; acc0.z += v0.z; acc0.w += v0.w;
    }
    acc0.x += acc1.x; acc0.y += acc1.y; acc0.z += acc1.z; acc0.w += acc1.w;

    float4 cv = *reinterpret_cast<const float4*>(&g_nc[node * 256 + 128 + lane * 4]);
    float4 bv = *reinterpret_cast<const float4*>(&bias[lane * 4]);
    float4 xr = *reinterpret_cast<const float4*>(&g_x[node * HH + lane * 4]);
    xr.x += EPS * tanhf(cv.x + acc0.x + bv.x);
    xr.y += EPS * tanhf(cv.y + acc0.y + bv.y);
    xr.z += EPS * tanhf(cv.z + acc0.z + bv.z);
    xr.w += EPS * tanhf(cv.w + acc0.w + bv.w);
    *reinterpret_cast<float4*>(&g_x[node * HH + lane * 4]) = xr;
}

// ---------------- pooling ----------------
__global__ void gstart_kernel(const int* __restrict__ batch) {
    int g = blockIdx.x * blockDim.x + threadIdx.x;
    if (g > GG) return;
    int lo = 0, hi = NN;
    while (lo < hi) {
        int mid = (lo + hi) >> 1;
        if (batch[mid] < g) lo = mid + 1; else hi = mid;
    }
    g_gstart[g] = lo;
}

__global__ void pool_kernel() {
    int g = blockIdx.x;
    int c = threadIdx.x;   // 0..127
    int s = g_gstart[g], e = g_gstart[g + 1];
    float sum = 0.f;
    float mx = -3.402823466e+38f;
    for (int i = s; i < e; i++) {
        float v = g_x[i * HH + c];
        sum += v;
        mx = fmaxf(mx, v);
    }
    int cnt = e - s;
    g_pooled[g * 384 + c] = sum;
    g_pooled[g * 384 + 128 + c] = (cnt > 0) ? mx : 0.f;
    g_pooled[g * 384 + 256 + c] = sum / fmaxf((float)cnt, 1.0f);
}

// ---------------- MLP head ----------------
__global__ void mlp1_kernel(const float* __restrict__ l1w, const float* __restrict__ l1b) {
    __shared__ float prow[384];
    int g = blockIdx.x;
    int j = threadIdx.x;   // 0..191
    for (int idx = j; idx < 384; idx += 192) prow[idx] = g_pooled[g * 384 + idx];
    __syncthreads();
    float acc = l1b[j];
    const float* wrow = &l1w[j * 384];
    #pragma unroll 8
    for (int k = 0; k < 384; k++) acc += prow[k] * wrow[k];
    g_h[g * 192 + j] = (acc > 0.f) ? acc : SLOPE * acc;
}

__global__ void mlp2_kernel(const float* __restrict__ l2w, const float* __restrict__ l2b,
                            float* __restrict__ out) {
    __shared__ float hrow[192];
    int g = blockIdx.x;
    int j = threadIdx.x;   // 0..63
    for (int idx = j; idx < 192; idx += 64) hrow[idx] = g_h[g * 192 + idx];
    __syncthreads();
    float acc = l2b[j];
    const float* wrow = &l2w[j * 192];
    #pragma unroll 8
    for (int k = 0; k < 192; k++) acc += hrow[k] * wrow[k];
    out[g * OUTD + j] = (acc > 0.f) ? acc : SLOPE * acc;
}

// ---------------- launch ----------------
extern "C" void kernel_launch(void* const* d_in, const int* in_sizes, int n_in,
                              void* d_out, int out_size) {
    const float* x_in  = (const float*)d_in[0];
    const int*   ei    = (const int*)d_in[1];   // [2,E] int32 (jax canonicalized)
    const int*   batch = (const int*)d_in[2];   // [N] int32
    const float* W     = (const float*)d_in[3];
    const float* bias  = (const float*)d_in[4];
    const float* lin_w = (const float*)d_in[5];
    const float* l1w   = (const float*)d_in[6];
    const float* l1b   = (const float*)d_in[7];
    const float* l2w   = (const float*)d_in[8];
    const float* l2b   = (const float*)d_in[9];
    float* out = (float*)d_out;

    // prep: weights, x copy, CSR by dst
    wcat_kernel<<<HH, 256>>>(W, lin_w);
    copy_x_kernel<<<(NN * HH / 4 + 255) / 256, 256>>>(x_in);
    zero_counts_kernel<<<(NN + 255) / 256, 256>>>();
    hist_kernel<<<(EE + 255) / 256, 256>>>(ei);
    scan_kernel<<<1, 1024>>>();
    fill_kernel<<<(EE + 255) / 256, 256>>>(ei);

    // 5 propagation iterations: fused GEMM + fused gather/update
    dim3 ggrid((NN + 63) / 64, 256 / 64);
    for (int it = 0; it < NITER; it++) {
        gemm_kernel<<<ggrid, 256>>>();
        agg_update_kernel<<<(NN * 32 + 255) / 256, 256>>>(bias);
    }

    // pooling + MLP head
    gstart_kernel<<<1, 512>>>(batch);
    pool_kernel<<<GG, HH>>>();
    mlp1_kernel<<<GG, 192>>>(l1w, l1b);
    mlp2_kernel<<<GG, OUTD>>>(l2w, l2b, out);
}

// round 3
// speedup vs baseline: 1.3322x; 1.3322x over previous
#include <cuda_runtime.h>
#include <cuda_bf16.h>
#include <cstdint>
#include <math.h>

#define NN 50000
#define HH 128
#define EE 600000
#define GG 256
#define OUTD 64
#define NITER 5
#define GAMMA 0.1f
#define EPS 0.1f
#define SLOPE 0.01f

// ---------------- device scratch (static, allocation-free) ----------------
__device__ float g_x[NN * HH];                 // working node features
__device__ float g_nc[NN * 256];               // [neigh(0:128) | conv_lin(128:256)]
__device__ __nv_bfloat16 g_Whi[256 * 128];     // W2 n-major [n][k], bf16 high part
__device__ __nv_bfloat16 g_Wlo[256 * 128];     // bf16 low part (residual)
__device__ int   g_counts[NN];
__device__ int   g_rowptr[NN + 1];
__device__ int   g_fillptr[NN];
__device__ int   g_srcsorted[EE];
__device__ int   g_gstart[GG + 1];
__device__ float g_pooled[GG * 384];
__device__ float g_h[GG * 192];

// ---------------- prep kernels ----------------
// W2[n][k]: n<128 -> lin_w[n,k] ; n>=128 -> A[n-128,k] = W[n-128,k]-W[k,n-128]-gamma*delta
__global__ void wprep_kernel(const float* __restrict__ W, const float* __restrict__ lin_w) {
    int n = blockIdx.x;      // 0..255
    int k = threadIdx.x;     // 0..127
    float v;
    if (n < 128) {
        v = lin_w[n * HH + k];
    } else {
        int np = n - 128;
        v = W[np * HH + k] - W[k * HH + np] - (np == k ? GAMMA : 0.0f);
    }
    __nv_bfloat16 hi = __float2bfloat16(v);
    __nv_bfloat16 lo = __float2bfloat16(v - __bfloat162float(hi));
    g_Whi[n * 128 + k] = hi;
    g_Wlo[n * 128 + k] = lo;
}

__global__ void copy_x_kernel(const float* __restrict__ xin) {
    int i = blockIdx.x * blockDim.x + threadIdx.x;
    if (i < NN * HH / 4) {
        reinterpret_cast<float4*>(g_x)[i] = reinterpret_cast<const float4*>(xin)[i];
    }
}

__global__ void zero_counts_kernel() {
    int i = blockIdx.x * blockDim.x + threadIdx.x;
    if (i < NN) g_counts[i] = 0;
}

__global__ void hist_kernel(const int* __restrict__ ei) {
    int e = blockIdx.x * blockDim.x + threadIdx.x;
    if (e < EE) {
        int dst = ei[EE + e];
        atomicAdd(&g_counts[dst], 1);
    }
}

__global__ void scan_kernel() {
    __shared__ int sh[1024];
    __shared__ int s_run;
    int t = threadIdx.x;
    if (t == 0) s_run = 0;
    __syncthreads();
    for (int base = 0; base < NN; base += 4096) {
        int i0 = base + t * 4;
        int v0 = (i0 + 0 < NN) ? g_counts[i0 + 0] : 0;
        int v1 = (i0 + 1 < NN) ? g_counts[i0 + 1] : 0;
        int v2 = (i0 + 2 < NN) ? g_counts[i0 + 2] : 0;
        int v3 = (i0 + 3 < NN) ? g_counts[i0 + 3] : 0;
        int s = v0 + v1 + v2 + v3;
        sh[t] = s;
        __syncthreads();
        #pragma unroll
        for (int off = 1; off < 1024; off <<= 1) {
            int add = (t >= off) ? sh[t - off] : 0;
            __syncthreads();
            sh[t] += add;
            __syncthreads();
        }
        int run = s_run;
        int acc = run + sh[t] - s;
        if (i0 + 0 < NN) { g_rowptr[i0 + 0] = acc; g_fillptr[i0 + 0] = acc; acc += v0; }
        if (i0 + 1 < NN) { g_rowptr[i0 + 1] = acc; g_fillptr[i0 + 1] = acc; acc += v1; }
        if (i0 + 2 < NN) { g_rowptr[i0 + 2] = acc; g_fillptr[i0 + 2] = acc; acc += v2; }
        if (i0 + 3 < NN) { g_rowptr[i0 + 3] = acc; g_fillptr[i0 + 3] = acc; acc += v3; }
        __syncthreads();
        if (t == 1023) s_run = run + sh[t];
        __syncthreads();
    }
    if (t == 0) g_rowptr[NN] = EE;
}

__global__ void fill_kernel(const int* __restrict__ ei) {
    int e = blockIdx.x * blockDim.x + threadIdx.x;
    if (e < EE) {
        int src = ei[e];
        int dst = ei[EE + e];
        int pos = atomicAdd(&g_fillptr[dst], 1);
        g_srcsorted[pos] = src;
    }
}

// ---------------- HMMA GEMM: g_nc = g_x [NN,128] @ W2^T [128,256] ----------------
// bf16 hi/lo split, fp32 accumulation via mma.sync.m16n8k16.
// CTA tile M=128, N=128, K=128. 8 warps (4M x 2N), warp tile 32x64.
// SMEM rows padded to 136 bf16 (272B) -> conflict-free fragment loads.
#define SROW 136
#define A_TILE_B (128 * SROW * 2)   // 34816
#define OFF_AHI 0
#define OFF_ALO (A_TILE_B)
#define OFF_BHI (2 * A_TILE_B)
#define OFF_BLO (3 * A_TILE_B)
#define SM_TOTAL (4 * A_TILE_B)     // 139264

__device__ __forceinline__ uint32_t bf2pack(float a, float b) {
    __nv_bfloat162 h2 = __floats2bfloat162_rn(a, b);
    return *reinterpret_cast<uint32_t*>(&h2);
}

__global__ __launch_bounds__(256, 1) void gemm_hmma_kernel() {
    extern __shared__ char sm[];
    __nv_bfloat16* sAhi = reinterpret_cast<__nv_bfloat16*>(sm + OFF_AHI);
    __nv_bfloat16* sAlo = reinterpret_cast<__nv_bfloat16*>(sm + OFF_ALO);
    __nv_bfloat16* sBhi = reinterpret_cast<__nv_bfloat16*>(sm + OFF_BHI);
    __nv_bfloat16* sBlo = reinterpret_cast<__nv_bfloat16*>(sm + OFF_BLO);

    int tid = threadIdx.x;
    int warp = tid >> 5;
    int lane = tid & 31;
    int rowbase = blockIdx.x * 128;
    int nbase = blockIdx.y * 128;

    // ---- load X tile [128][128] f32, split to bf16 hi/lo ----
    {
        int r = tid >> 1;
        int kh = (tid & 1) * 64;
        int grow = rowbase + r;
        const float4* xrow = reinterpret_cast<const float4*>(&g_x[(size_t)grow * HH + kh]);
        uint32_t* dh = reinterpret_cast<uint32_t*>(&sAhi[r * SROW + kh]);
        uint32_t* dl = reinterpret_cast<uint32_t*>(&sAlo[r * SROW + kh]);
        #pragma unroll
        for (int q = 0; q < 16; q++) {
            float4 f = (grow < NN) ? xrow[q] : make_float4(0.f, 0.f, 0.f, 0.f);
            uint32_t h0 = bf2pack(f.x, f.y);
            uint32_t h1 = bf2pack(f.z, f.w);
            __nv_bfloat162 hh0 = *reinterpret_cast<__nv_bfloat162*>(&h0);
            __nv_bfloat162 hh1 = *reinterpret_cast<__nv_bfloat162*>(&h1);
            uint32_t l0 = bf2pack(f.x - __bfloat162float(hh0.x), f.y - __bfloat162float(hh0.y));
            uint32_t l1 = bf2pack(f.z - __bfloat162float(hh1.x), f.w - __bfloat162float(hh1.y));
            dh[2 * q + 0] = h0; dh[2 * q + 1] = h1;
            dl[2 * q + 0] = l0; dl[2 * q + 1] = l1;
        }
    }
    // ---- load W tile (n-major, already bf16) ----
    {
        int n = tid >> 1;
        int kh = (tid & 1) * 64;
        const uint4* whsrc = reinterpret_cast<const uint4*>(&g_Whi[(nbase + n) * 128 + kh]);
        const uint4* wlsrc = reinterpret_cast<const uint4*>(&g_Wlo[(nbase + n) * 128 + kh]);
        uint4* dh = reinterpret_cast<uint4*>(&sBhi[n * SROW + kh]);
        uint4* dl = reinterpret_cast<uint4*>(&sBlo[n * SROW + kh]);
        #pragma unroll
        for (int q = 0; q < 8; q++) {
            dh[q] = whsrc[q];
            dl[q] = wlsrc[q];
        }
    }
    __syncthreads();

    // ---- compute: warp tile 32 (M) x 64 (N) ----
    int mrow = (warp & 3) * 32;
    int ncol = (warp >> 2) * 64;
    int g = lane >> 2;
    int tig = lane & 3;

    float acc[2][8][4];
    #pragma unroll
    for (int mt = 0; mt < 2; mt++)
        #pragma unroll
        for (int nt = 0; nt < 8; nt++)
            #pragma unroll
            for (int q = 0; q < 4; q++) acc[mt][nt][q] = 0.f;

    #pragma unroll 1
    for (int term = 0; term < 3; term++) {
        const __nv_bfloat16* A = (term == 1) ? sAlo : sAhi;
        const __nv_bfloat16* B = (term == 2) ? sBlo : sBhi;
        #pragma unroll
        for (int ks = 0; ks < 8; ks++) {
            int kc = ks * 16 + 2 * tig;
            uint32_t a[2][4];
            #pragma unroll
            for (int mt = 0; mt < 2; mt++) {
                int rb = mrow + mt * 16 + g;
                a[mt][0] = *reinterpret_cast<const uint32_t*>(&A[rb * SROW + kc]);
                a[mt][1] = *reinterpret_cast<const uint32_t*>(&A[(rb + 8) * SROW + kc]);
                a[mt][2] = *reinterpret_cast<const uint32_t*>(&A[rb * SROW + kc + 8]);
                a[mt][3] = *reinterpret_cast<const uint32_t*>(&A[(rb + 8) * SROW + kc + 8]);
            }
            uint32_t b[8][2];
            #pragma unroll
            for (int nt = 0; nt < 8; nt++) {
                int cb = ncol + nt * 8 + g;
                b[nt][0] = *reinterpret_cast<const uint32_t*>(&B[cb * SROW + kc]);
                b[nt][1] = *reinterpret_cast<const uint32_t*>(&B[cb * SROW + kc + 8]);
            }
            #pragma unroll
            for (int mt = 0; mt < 2; mt++) {
                #pragma unroll
                for (int nt = 0; nt < 8; nt++) {
                    asm volatile(
                        "mma.sync.aligned.m16n8k16.row.col.f32.bf16.bf16.f32 "
                        "{%0,%1,%2,%3}, {%4,%5,%6,%7}, {%8,%9}, {%0,%1,%2,%3};"
                        : "+f"(acc[mt][nt][0]), "+f"(acc[mt][nt][1]),
                          "+f"(acc[mt][nt][2]), "+f"(acc[mt][nt][3])
                        : "r"(a[mt][0]), "r"(a[mt][1]), "r"(a[mt][2]), "r"(a[mt][3]),
                          "r"(b[nt][0]), "r"(b[nt][1]));
                }
            }
        }
    }

    // ---- epilogue: write fp32 results to g_nc ----
    #pragma unroll
    for (int mt = 0; mt < 2; mt++) {
        int r0 = rowbase + mrow + mt * 16 + g;
        int r1 = r0 + 8;
        #pragma unroll
        for (int nt = 0; nt < 8; nt++) {
            int col = nbase + ncol + nt * 8 + 2 * tig;
            if (r0 < NN) {
                *reinterpret_cast<float2*>(&g_nc[(size_t)r0 * 256 + col]) =
                    make_float2(acc[mt][nt][0], acc[mt][nt][1]);
            }
            if (r1 < NN) {
                *reinterpret_cast<float2*>(&g_nc[(size_t)r1 * 256 + col]) =
                    make_float2(acc[mt][nt][2], acc[mt][nt][3]);
            }
        }
    }
}

// ---------------- fused aggregate + conv + tanh + x update (warp per node) ----------------
__global__ __launch_bounds__(256) void agg_update_kernel(const float* __restrict__ bias) {
    int node = (blockIdx.x * blockDim.x + threadIdx.x) >> 5;
    int lane = threadIdx.x & 31;
    if (node >= NN) return;
    int s = g_rowptr[node];
    int e = g_rowptr[node + 1];
    float4 acc0 = make_float4(0.f, 0.f, 0.f, 0.f);
    float4 acc1 = make_float4(0.f, 0.f, 0.f, 0.f);
    int p = s;
    for (; p + 1 < e; p += 2) {
        int s0 = g_srcsorted[p];
        int s1 = g_srcsorted[p + 1];
        float4 v0 = *reinterpret_cast<const float4*>(&g_nc[(size_t)s0 * 256 + lane * 4]);
        float4 v1 = *reinterpret_cast<const float4*>(&g_nc[(size_t)s1 * 256 + lane * 4]);
        acc0.x += v0.x; acc0.y += v0.y; acc0.z += v0.z; acc0.w += v0.w;
        acc1.x += v1.x; acc1.y += v1.y; acc1.z += v1.z; acc1.w += v1.w;
    }
    if (p < e) {
        int s0 = g_srcsorted[p];
        float4 v0 = *reinterpret_cast<const float4*>(&g_nc[(size_t)s0 * 256 + lane * 4]);
        acc0.x += v0.x; acc0.y += v0.y; acc0.z += v0.z; acc0.w += v0.w;
    }
    acc0.x += acc1.x; acc0.y += acc1.y; acc0.z += acc1.z; acc0.w += acc1.w;

    float4 cv = *reinterpret_cast<const float4*>(&g_nc[(size_t)node * 256 + 128 + lane * 4]);
    float4 bv = *reinterpret_cast<const float4*>(&bias[lane * 4]);
    float4 xr = *reinterpret_cast<const float4*>(&g_x[(size_t)node * HH + lane * 4]);
    xr.x += EPS * tanhf(cv.x + acc0.x + bv.x);
    xr.y += EPS * tanhf(cv.y + acc0.y + bv.y);
    xr.z += EPS * tanhf(cv.z + acc0.z + bv.z);
    xr.w += EPS * tanhf(cv.w + acc0.w + bv.w);
    *reinterpret_cast<float4*>(&g_x[(size_t)node * HH + lane * 4]) = xr;
}

// ---------------- pooling ----------------
__global__ void gstart_kernel(const int* __restrict__ batch) {
    int g = blockIdx.x * blockDim.x + threadIdx.x;
    if (g > GG) return;
    int lo = 0, hi = NN;
    while (lo < hi) {
        int mid = (lo + hi) >> 1;
        if (batch[mid] < g) lo = mid + 1; else hi = mid;
    }
    g_gstart[g] = lo;
}

__global__ void pool_kernel() {
    int g = blockIdx.x;
    int c = threadIdx.x;   // 0..127
    int s = g_gstart[g], e = g_gstart[g + 1];
    float sum = 0.f;
    float mx = -3.402823466e+38f;
    for (int i = s; i < e; i++) {
        float v = g_x[(size_t)i * HH + c];
        sum += v;
        mx = fmaxf(mx, v);
    }
    int cnt = e - s;
    g_pooled[g * 384 + c] = sum;
    g_pooled[g * 384 + 128 + c] = (cnt > 0) ? mx : 0.f;
    g_pooled[g * 384 + 256 + c] = sum / fmaxf((float)cnt, 1.0f);
}

// ---------------- MLP head ----------------
__global__ void mlp1_kernel(const float* __restrict__ l1w, const float* __restrict__ l1b) {
    __shared__ float prow[384];
    int g = blockIdx.x;
    int j = threadIdx.x;   // 0..191
    for (int idx = j; idx < 384; idx += 192) prow[idx] = g_pooled[g * 384 + idx];
    __syncthreads();
    float acc = l1b[j];
    const float* wrow = &l1w[j * 384];
    #pragma unroll 8
    for (int k = 0; k < 384; k++) acc += prow[k] * wrow[k];
    g_h[g * 192 + j] = (acc > 0.f) ? acc : SLOPE * acc;
}

__global__ void mlp2_kernel(const float* __restrict__ l2w, const float* __restrict__ l2b,
                            float* __restrict__ out) {
    __shared__ float hrow[192];
    int g = blockIdx.x;
    int j = threadIdx.x;   // 0..63
    for (int idx = j; idx < 192; idx += 64) hrow[idx] = g_h[g * 192 + idx];
    __syncthreads();
    float acc = l2b[j];
    const float* wrow = &l2w[j * 192];
    #pragma unroll 8
    for (int k = 0; k < 192; k++) acc += hrow[k] * wrow[k];
    out[g * OUTD + j] = (acc > 0.f) ? acc : SLOPE * acc;
}

// ---------------- launch ----------------
extern "C" void kernel_launch(void* const* d_in, const int* in_sizes, int n_in,
                              void* d_out, int out_size) {
    const float* x_in  = (const float*)d_in[0];
    const int*   ei    = (const int*)d_in[1];   // [2,E] int32
    const int*   batch = (const int*)d_in[2];   // [N] int32
    const float* W     = (const float*)d_in[3];
    const float* bias  = (const float*)d_in[4];
    const float* lin_w = (const float*)d_in[5];
    const float* l1w   = (const float*)d_in[6];
    const float* l1b   = (const float*)d_in[7];
    const float* l2w   = (const float*)d_in[8];
    const float* l2b   = (const float*)d_in[9];
    float* out = (float*)d_out;

    cudaFuncSetAttribute(gemm_hmma_kernel, cudaFuncAttributeMaxDynamicSharedMemorySize, SM_TOTAL);

    // prep: weights (bf16 hi/lo, n-major), x copy, CSR by dst
    wprep_kernel<<<256, 128>>>(W, lin_w);
    copy_x_kernel<<<(NN * HH / 4 + 255) / 256, 256>>>(x_in);
    zero_counts_kernel<<<(NN + 255) / 256, 256>>>();
    hist_kernel<<<(EE + 255) / 256, 256>>>(ei);
    scan_kernel<<<1, 1024>>>();
    fill_kernel<<<(EE + 255) / 256, 256>>>(ei);

    // 5 propagation iterations: HMMA GEMM + fused gather/update
    dim3 ggrid((NN + 127) / 128, 2);
    for (int it = 0; it < NITER; it++) {
        gemm_hmma_kernel<<<ggrid, 256, SM_TOTAL>>>();
        agg_update_kernel<<<(NN * 32 + 255) / 256, 256>>>(bias);
    }

    // pooling + MLP head
    gstart_kernel<<<1, 512>>>(batch);
    pool_kernel<<<GG, HH>>>();
    mlp1_kernel<<<GG, 192>>>(l1w, l1b);
    mlp2_kernel<<<GG, OUTD>>>(l2w, l2b, out);
}

// round 4
// speedup vs baseline: 1.5880x; 1.1920x over previous
#include <cuda_runtime.h>
#include <cuda_bf16.h>
#include <cstdint>
#include <math.h>

#define NN 50000
#define HH 128
#define EE 600000
#define GG 256
#define OUTD 64
#define NITER 5
#define GAMMA 0.1f
#define EPS 0.1f
#define SLOPE 0.01f

// ---------------- device scratch (static, allocation-free) ----------------
__device__ float g_x[NN * HH];                 // working node features (fp32)
__device__ __nv_bfloat16 g_xhi[NN * HH];       // bf16 split of x, high
__device__ __nv_bfloat16 g_xlo[NN * HH];       // bf16 split of x, low
__device__ float g_nc[NN * 256];               // [neigh(0:128) | conv_lin(128:256)]
__device__ __nv_bfloat16 g_Whi[256 * 128];     // W2 n-major [n][k], bf16 high
__device__ __nv_bfloat16 g_Wlo[256 * 128];     // bf16 low (residual)
__device__ int   g_counts[NN];
__device__ int   g_rowptr[NN + 1];
__device__ int   g_fillptr[NN];
__device__ int   g_srcsorted[EE];
__device__ int   g_gstart[GG + 1];
__device__ float g_pooled[GG * 384];
__device__ float g_h[GG * 192];

__device__ __forceinline__ uint32_t smem_u32(const void* p) {
    uint32_t a;
    asm("{ .reg .u64 t; cvta.to.shared.u64 t, %1; cvt.u32.u64 %0, t; }" : "=r"(a) : "l"(p));
    return a;
}

__device__ __forceinline__ uint32_t bf2pack(float a, float b) {
    __nv_bfloat162 h2 = __floats2bfloat162_rn(a, b);
    return *reinterpret_cast<uint32_t*>(&h2);
}

// ---------------- prep kernels ----------------
__global__ void wprep_kernel(const float* __restrict__ W, const float* __restrict__ lin_w) {
    int n = blockIdx.x;      // 0..255
    int k = threadIdx.x;     // 0..127
    float v;
    if (n < 128) {
        v = lin_w[n * HH + k];
    } else {
        int np = n - 128;
        v = W[np * HH + k] - W[k * HH + np] - (np == k ? GAMMA : 0.0f);
    }
    __nv_bfloat16 hi = __float2bfloat16(v);
    __nv_bfloat16 lo = __float2bfloat16(v - __bfloat162float(hi));
    g_Whi[n * 128 + k] = hi;
    g_Wlo[n * 128 + k] = lo;
}

__global__ void copy_x_kernel(const float* __restrict__ xin) {
    int i = blockIdx.x * blockDim.x + threadIdx.x;
    if (i < NN * HH / 4) {
        float4 f = reinterpret_cast<const float4*>(xin)[i];
        reinterpret_cast<float4*>(g_x)[i] = f;
        uint32_t h0 = bf2pack(f.x, f.y);
        uint32_t h1 = bf2pack(f.z, f.w);
        __nv_bfloat162 hh0 = *reinterpret_cast<__nv_bfloat162*>(&h0);
        __nv_bfloat162 hh1 = *reinterpret_cast<__nv_bfloat162*>(&h1);
        uint32_t l0 = bf2pack(f.x - __bfloat162float(hh0.x), f.y - __bfloat162float(hh0.y));
        uint32_t l1 = bf2pack(f.z - __bfloat162float(hh1.x), f.w - __bfloat162float(hh1.y));
        reinterpret_cast<uint2*>(g_xhi)[i] = make_uint2(h0, h1);
        reinterpret_cast<uint2*>(g_xlo)[i] = make_uint2(l0, l1);
    }
}

__global__ void zero_counts_kernel() {
    int i = blockIdx.x * blockDim.x + threadIdx.x;
    if (i < NN) g_counts[i] = 0;
}

__global__ void hist_kernel(const int* __restrict__ ei) {
    int e = blockIdx.x * blockDim.x + threadIdx.x;
    if (e < EE) {
        int dst = ei[EE + e];
        atomicAdd(&g_counts[dst], 1);
    }
}

__global__ void scan_kernel() {
    __shared__ int sh[1024];
    __shared__ int s_run;
    int t = threadIdx.x;
    if (t == 0) s_run = 0;
    __syncthreads();
    for (int base = 0; base < NN; base += 4096) {
        int i0 = base + t * 4;
        int v0 = (i0 + 0 < NN) ? g_counts[i0 + 0] : 0;
        int v1 = (i0 + 1 < NN) ? g_counts[i0 + 1] : 0;
        int v2 = (i0 + 2 < NN) ? g_counts[i0 + 2] : 0;
        int v3 = (i0 + 3 < NN) ? g_counts[i0 + 3] : 0;
        int s = v0 + v1 + v2 + v3;
        sh[t] = s;
        __syncthreads();
        #pragma unroll
        for (int off = 1; off < 1024; off <<= 1) {
            int add = (t >= off) ? sh[t - off] : 0;
            __syncthreads();
            sh[t] += add;
            __syncthreads();
        }
        int run = s_run;
        int acc = run + sh[t] - s;
        if (i0 + 0 < NN) { g_rowptr[i0 + 0] = acc; g_fillptr[i0 + 0] = acc; acc += v0; }
        if (i0 + 1 < NN) { g_rowptr[i0 + 1] = acc; g_fillptr[i0 + 1] = acc; acc += v1; }
        if (i0 + 2 < NN) { g_rowptr[i0 + 2] = acc; g_fillptr[i0 + 2] = acc; acc += v2; }
        if (i0 + 3 < NN) { g_rowptr[i0 + 3] = acc; g_fillptr[i0 + 3] = acc; acc += v3; }
        __syncthreads();
        if (t == 1023) s_run = run + sh[t];
        __syncthreads();
    }
    if (t == 0) g_rowptr[NN] = EE;
}

__global__ void fill_kernel(const int* __restrict__ ei) {
    int e = blockIdx.x * blockDim.x + threadIdx.x;
    if (e < EE) {
        int src = ei[e];
        int dst = ei[EE + e];
        int pos = atomicAdd(&g_fillptr[dst], 1);
        g_srcsorted[pos] = src;
    }
}

// ---------------- HMMA GEMM: g_nc = x [NN,128] @ W2^T [128,256] ----------------
// bf16 hi/lo split (Ahi*Bhi + Alo*Bhi + Ahi*Blo), fp32 accum, mma.sync m16n8k16.
// CTA tile M=128, N=64, K=128. 8 warps (4M x 2N), warp tile 32x32.
// SMEM rows padded to 136 bf16 (272B): ldmatrix conflict-free. 2 CTAs/SM.
#define SROWB 272
#define OFF_AHI 0
#define OFF_ALO 34816                 // 128*272
#define OFF_BHI 69632
#define OFF_BLO 87040                 // 69632 + 64*272
#define SM_TOTAL 104448               // 87040 + 64*272

#define LDM_X4(d, addr) \
    asm volatile("ldmatrix.sync.aligned.m8n8.x4.shared.b16 {%0,%1,%2,%3}, [%4];" \
        : "=r"((d)[0]), "=r"((d)[1]), "=r"((d)[2]), "=r"((d)[3]) : "r"(addr))

#define MMA_BF16(c, a, b) \
    asm volatile("mma.sync.aligned.m16n8k16.row.col.f32.bf16.bf16.f32 " \
        "{%0,%1,%2,%3}, {%4,%5,%6,%7}, {%8,%9}, {%0,%1,%2,%3};" \
        : "+f"((c)[0]), "+f"((c)[1]), "+f"((c)[2]), "+f"((c)[3]) \
        : "r"((a)[0]), "r"((a)[1]), "r"((a)[2]), "r"((a)[3]), "r"((b)[0]), "r"((b)[1]))

__device__ __forceinline__ void cp16(uint32_t dst, const void* src, uint32_t srcsize) {
    asm volatile("cp.async.ca.shared.global [%0], [%1], 16, %2;"
                 :: "r"(dst), "l"(src), "r"(srcsize) : "memory");
}

__global__ __launch_bounds__(256, 2) void gemm_hmma_kernel() {
    extern __shared__ char sm[];
    uint32_t sb = smem_u32(sm);
    int tid = threadIdx.x;
    int warp = tid >> 5;
    int lane = tid & 31;
    int rowbase = blockIdx.x * 128;
    int nbase = blockIdx.y * 64;

    // ---- async loads: A (hi/lo) 128x128 bf16, B (hi/lo) 64x128 bf16 ----
    #pragma unroll
    for (int p = 0; p < 8; p++) {
        int j = tid + p * 256;         // 0..2047
        int row = j >> 4;
        int c = j & 15;
        int gr = rowbase + row;
        uint32_t ok = (gr < NN) ? 16u : 0u;
        int grc = (gr < NN) ? gr : 0;
        uint32_t doff = (uint32_t)(row * SROWB + c * 16);
        cp16(sb + OFF_AHI + doff, &g_xhi[(size_t)grc * 128 + c * 8], ok);
        cp16(sb + OFF_ALO + doff, &g_xlo[(size_t)grc * 128 + c * 8], ok);
    }
    #pragma unroll
    for (int p = 0; p < 4; p++) {
        int j = tid + p * 256;         // 0..1023
        int row = j >> 4;
        int c = j & 15;
        uint32_t doff = (uint32_t)(row * SROWB + c * 16);
        cp16(sb + OFF_BHI + doff, &g_Whi[(size_t)(nbase + row) * 128 + c * 8], 16u);
        cp16(sb + OFF_BLO + doff, &g_Wlo[(size_t)(nbase + row) * 128 + c * 8], 16u);
    }
    asm volatile("cp.async.commit_group;");
    asm volatile("cp.async.wait_group 0;");
    __syncthreads();

    // ---- compute: warp tile 32(M) x 32(N) ----
    int mrow = (warp & 3) * 32;
    int ncol = (warp >> 2) * 32;
    int g = lane >> 2;
    int tig = lane & 3;

    // ldmatrix address offsets
    uint32_t aoffA = (uint32_t)((mrow + (lane & 15)) * SROWB + (lane >> 4) * 16);
    int bm = lane >> 3;
    uint32_t aoffB = (uint32_t)((ncol + ((bm >> 1) << 3) + (lane & 7)) * SROWB + (bm & 1) * 16);

    float acc[2][4][4];
    #pragma unroll
    for (int mt = 0; mt < 2; mt++)
        #pragma unroll
        for (int nt = 0; nt < 4; nt++)
            #pragma unroll
            for (int q = 0; q < 4; q++) acc[mt][nt][q] = 0.f;

    #pragma unroll
    for (int ks = 0; ks < 8; ks++) {
        uint32_t kb = (uint32_t)(ks * 32);
        uint32_t ahi[2][4], alo[2][4], bhi[2][4], blo[2][4];
        #pragma unroll
        for (int mt = 0; mt < 2; mt++) {
            LDM_X4(ahi[mt], sb + OFF_AHI + aoffA + mt * 16 * SROWB + kb);
            LDM_X4(alo[mt], sb + OFF_ALO + aoffA + mt * 16 * SROWB + kb);
        }
        #pragma unroll
        for (int pr = 0; pr < 2; pr++) {
            LDM_X4(bhi[pr], sb + OFF_BHI + aoffB + pr * 16 * SROWB + kb);
            LDM_X4(blo[pr], sb + OFF_BLO + aoffB + pr * 16 * SROWB + kb);
        }
        #pragma unroll
        for (int mt = 0; mt < 2; mt++) {
            #pragma unroll
            for (int nt = 0; nt < 4; nt++) {
                uint32_t bh[2] = {bhi[nt >> 1][(nt & 1) * 2], bhi[nt >> 1][(nt & 1) * 2 + 1]};
                uint32_t bl[2] = {blo[nt >> 1][(nt & 1) * 2], blo[nt >> 1][(nt & 1) * 2 + 1]};
                MMA_BF16(acc[mt][nt], ahi[mt], bh);
                MMA_BF16(acc[mt][nt], alo[mt], bh);
                MMA_BF16(acc[mt][nt], ahi[mt], bl);
            }
        }
    }

    // ---- epilogue ----
    #pragma unroll
    for (int mt = 0; mt < 2; mt++) {
        int r0 = rowbase + mrow + mt * 16 + g;
        int r1 = r0 + 8;
        #pragma unroll
        for (int nt = 0; nt < 4; nt++) {
            int col = nbase + ncol + nt * 8 + 2 * tig;
            if (r0 < NN) {
                *reinterpret_cast<float2*>(&g_nc[(size_t)r0 * 256 + col]) =
                    make_float2(acc[mt][nt][0], acc[mt][nt][1]);
            }
            if (r1 < NN) {
                *reinterpret_cast<float2*>(&g_nc[(size_t)r1 * 256 + col]) =
                    make_float2(acc[mt][nt][2], acc[mt][nt][3]);
            }
        }
    }
}

// ---------------- fused aggregate + conv + tanh + x update (warp per node) ----------------
__global__ __launch_bounds__(256) void agg_update_kernel(const float* __restrict__ bias) {
    int node = (blockIdx.x * blockDim.x + threadIdx.x) >> 5;
    int lane = threadIdx.x & 31;
    if (node >= NN) return;
    int s = g_rowptr[node];
    int e = g_rowptr[node + 1];
    float4 acc0 = make_float4(0.f, 0.f, 0.f, 0.f);
    float4 acc1 = make_float4(0.f, 0.f, 0.f, 0.f);
    int p = s;
    for (; p + 1 < e; p += 2) {
        int s0 = g_srcsorted[p];
        int s1 = g_srcsorted[p + 1];
        float4 v0 = *reinterpret_cast<const float4*>(&g_nc[(size_t)s0 * 256 + lane * 4]);
        float4 v1 = *reinterpret_cast<const float4*>(&g_nc[(size_t)s1 * 256 + lane * 4]);
        acc0.x += v0.x; acc0.y += v0.y; acc0.z += v0.z; acc0.w += v0.w;
        acc1.x += v1.x; acc1.y += v1.y; acc1.z += v1.z; acc1.w += v1.w;
    }
    if (p < e) {
        int s0 = g_srcsorted[p];
        float4 v0 = *reinterpret_cast<const float4*>(&g_nc[(size_t)s0 * 256 + lane * 4]);
        acc0.x += v0.x; acc0.y += v0.y; acc0.z += v0.z; acc0.w += v0.w;
    }
    acc0.x += acc1.x; acc0.y += acc1.y; acc0.z += acc1.z; acc0.w += acc1.w;

    float4 cv = *reinterpret_cast<const float4*>(&g_nc[(size_t)node * 256 + 128 + lane * 4]);
    float4 bv = *reinterpret_cast<const float4*>(&bias[lane * 4]);
    float4 xr = *reinterpret_cast<const float4*>(&g_x[(size_t)node * HH + lane * 4]);
    xr.x += EPS * tanhf(cv.x + acc0.x + bv.x);
    xr.y += EPS * tanhf(cv.y + acc0.y + bv.y);
    xr.z += EPS * tanhf(cv.z + acc0.z + bv.z);
    xr.w += EPS * tanhf(cv.w + acc0.w + bv.w);
    *reinterpret_cast<float4*>(&g_x[(size_t)node * HH + lane * 4]) = xr;

    // bf16 hi/lo split for next GEMM
    uint32_t h0 = bf2pack(xr.x, xr.y);
    uint32_t h1 = bf2pack(xr.z, xr.w);
    __nv_bfloat162 hh0 = *reinterpret_cast<__nv_bfloat162*>(&h0);
    __nv_bfloat162 hh1 = *reinterpret_cast<__nv_bfloat162*>(&h1);
    uint32_t l0 = bf2pack(xr.x - __bfloat162float(hh0.x), xr.y - __bfloat162float(hh0.y));
    uint32_t l1 = bf2pack(xr.z - __bfloat162float(hh1.x), xr.w - __bfloat162float(hh1.y));
    *reinterpret_cast<uint2*>(&g_xhi[(size_t)node * HH + lane * 4]) = make_uint2(h0, h1);
    *reinterpret_cast<uint2*>(&g_xlo[(size_t)node * HH + lane * 4]) = make_uint2(l0, l1);
}

// ---------------- pooling ----------------
__global__ void gstart_kernel(const int* __restrict__ batch) {
    int g = blockIdx.x * blockDim.x + threadIdx.x;
    if (g > GG) return;
    int lo = 0, hi = NN;
    while (lo < hi) {
        int mid = (lo + hi) >> 1;
        if (batch[mid] < g) lo = mid + 1; else hi = mid;
    }
    g_gstart[g] = lo;
}

__global__ void pool_kernel() {
    int g = blockIdx.x;
    int c = threadIdx.x;   // 0..127
    int s = g_gstart[g], e = g_gstart[g + 1];
    float sum = 0.f;
    float mx = -3.402823466e+38f;
    for (int i = s; i < e; i++) {
        float v = g_x[(size_t)i * HH + c];
        sum += v;
        mx = fmaxf(mx, v);
    }
    int cnt = e - s;
    g_pooled[g * 384 + c] = sum;
    g_pooled[g * 384 + 128 + c] = (cnt > 0) ? mx : 0.f;
    g_pooled[g * 384 + 256 + c] = sum / fmaxf((float)cnt, 1.0f);
}

// ---------------- MLP head ----------------
__global__ void mlp1_kernel(const float* __restrict__ l1w, const float* __restrict__ l1b) {
    __shared__ float prow[384];
    int g = blockIdx.x;
    int j = threadIdx.x;   // 0..191
    for (int idx = j; idx < 384; idx += 192) prow[idx] = g_pooled[g * 384 + idx];
    __syncthreads();
    float acc = l1b[j];
    const float* wrow = &l1w[j * 384];
    #pragma unroll 8
    for (int k = 0; k < 384; k++) acc += prow[k] * wrow[k];
    g_h[g * 192 + j] = (acc > 0.f) ? acc : SLOPE * acc;
}

__global__ void mlp2_kernel(const float* __restrict__ l2w, const float* __restrict__ l2b,
                            float* __restrict__ out) {
    __shared__ float hrow[192];
    int g = blockIdx.x;
    int j = threadIdx.x;   // 0..63
    for (int idx = j; idx < 192; idx += 64) hrow[idx] = g_h[g * 192 + idx];
    __syncthreads();
    float acc = l2b[j];
    const float* wrow = &l2w[j * 192];
    #pragma unroll 8
    for (int k = 0; k < 192; k++) acc += hrow[k] * wrow[k];
    out[g * OUTD + j] = (acc > 0.f) ? acc : SLOPE * acc;
}

// ---------------- launch ----------------
extern "C" void kernel_launch(void* const* d_in, const int* in_sizes, int n_in,
                              void* d_out, int out_size) {
    const float* x_in  = (const float*)d_in[0];
    const int*   ei    = (const int*)d_in[1];   // [2,E] int32
    const int*   batch = (const int*)d_in[2];   // [N] int32
    const float* W     = (const float*)d_in[3];
    const float* bias  = (const float*)d_in[4];
    const float* lin_w = (const float*)d_in[5];
    const float* l1w   = (const float*)d_in[6];
    const float* l1b   = (const float*)d_in[7];
    const float* l2w   = (const float*)d_in[8];
    const float* l2b   = (const float*)d_in[9];
    float* out = (float*)d_out;

    cudaFuncSetAttribute(gemm_hmma_kernel, cudaFuncAttributeMaxDynamicSharedMemorySize, SM_TOTAL);

    // prep
    wprep_kernel<<<256, 128>>>(W, lin_w);
    copy_x_kernel<<<(NN * HH / 4 + 255) / 256, 256>>>(x_in);
    zero_counts_kernel<<<(NN + 255) / 256, 256>>>();
    hist_kernel<<<(EE + 255) / 256, 256>>>(ei);
    scan_kernel<<<1, 1024>>>();
    fill_kernel<<<(EE + 255) / 256, 256>>>(ei);

    // 5 propagation iterations
    dim3 ggrid((NN + 127) / 128, 4);
    for (int it = 0; it < NITER; it++) {
        gemm_hmma_kernel<<<ggrid, 256, SM_TOTAL>>>();
        agg_update_kernel<<<(NN * 32 + 255) / 256, 256>>>(bias);
    }

    // pooling + MLP head
    gstart_kernel<<<1, 512>>>(batch);
    pool_kernel<<<GG, HH>>>();
    mlp1_kernel<<<GG, 192>>>(l1w, l1b);
    mlp2_kernel<<<GG, OUTD>>>(l2w, l2b, out);
}